// round 13
// baseline (speedup 1.0000x reference)
#include <cuda_runtime.h>
#include <cuda_bf16.h>
#include <cstdint>

#define NODES    100000
#define NODES_PAD 100096          // 782 * 128
#define C        256
#define GRAPHS   64
#define OUTC     10
#define EMAX     1600000
#define NB1024   ((NODES + 1023) / 1024)

// ---------------- scratch (static device globals; no allocation) ----------
__device__ __align__(16) __nv_bfloat16 g_A[(size_t)NODES_PAD * C];  // bf16(x*dinv)
__device__ __align__(16) __nv_bfloat16 g_B[(size_t)C * C];          // bf16(W1^T)
__device__ __align__(16) uint32_t g_hsb[(size_t)NODES_PAD * (C / 2)]; // bf16x2
__device__ float g_dinv[NODES];
__device__ int   g_degi[NODES];
__device__ int   g_rowptr[NODES + 1];
__device__ int   g_cursor[NODES];
__device__ int   g_elist[EMAX];
__device__ int   g_bsum[NB1024 + 1];
__device__ float g_sums[GRAPHS * C];
__device__ float g_counts[GRAPHS];
__device__ int   g_is64;

// ---------------- helpers ------------------------------------------------
__device__ __forceinline__ int load_idx(const void* p, long long i, int is64) {
    if (is64) return (int)((const long long*)p)[i];
    return ((const int*)p)[i];
}

__device__ __forceinline__ void mma16816(float* c, const uint32_t* a,
                                         const uint32_t* b) {
    asm volatile(
        "mma.sync.aligned.m16n8k16.row.col.f32.bf16.bf16.f32 "
        "{%0,%1,%2,%3}, {%4,%5,%6,%7}, {%8,%9}, {%0,%1,%2,%3};"
        : "+f"(c[0]), "+f"(c[1]), "+f"(c[2]), "+f"(c[3])
        : "r"(a[0]), "r"(a[1]), "r"(a[2]), "r"(a[3]), "r"(b[0]), "r"(b[1]));
}

__device__ __forceinline__ uint32_t smem_u32(const void* p) {
    uint32_t a;
    asm("{ .reg .u64 t; cvta.to.shared.u64 t, %1; cvt.u32.u64 %0, t; }"
        : "=r"(a) : "l"(p));
    return a;
}
__device__ __forceinline__ void cp16(uint32_t dst, const void* src) {
    asm volatile("cp.async.ca.shared.global [%0], [%1], 16;"
                 :: "r"(dst), "l"(src) : "memory");
}
#define CP_COMMIT() asm volatile("cp.async.commit_group;" ::: "memory")
#define CP_WAIT(N)  asm volatile("cp.async.wait_group %0;" :: "n"(N) : "memory")

// ---------------------------------------------------------------------------
__global__ void detect_kernel(const int* __restrict__ ei32) {
    if (threadIdx.x == 0 && blockIdx.x == 0) {
        int nz = 0;
        #pragma unroll
        for (int i = 1; i < 256; i += 2) nz |= (ei32[i] != 0);
        g_is64 = (nz == 0) ? 1 : 0;
    }
}

__global__ void init_kernel(int n) {
    int i = blockIdx.x * blockDim.x + threadIdx.x;
    if (i < n) g_degi[i] = 0;
    if (i < GRAPHS * C) g_sums[i] = 0.f;
    if (i < GRAPHS) g_counts[i] = 0.f;
}

__global__ void degi_kernel(const void* __restrict__ ei, int E) {
    int i = blockIdx.x * blockDim.x + threadIdx.x;
    if (i >= E) return;
    int d = load_idx(ei, (long long)E + i, g_is64);
    atomicAdd(&g_degi[d], 1);
}

// ---------------- hierarchical scan ----------------------------------------
__global__ void scan1_kernel(int n) {
    __shared__ int wsum[32];
    int t = threadIdx.x;
    int i = blockIdx.x * 1024 + t;
    int v = (i < n) ? g_degi[i] : 0;
    int lane = t & 31, w = t >> 5;
    int inc = v;
    #pragma unroll
    for (int d = 1; d < 32; d <<= 1) {
        int u = __shfl_up_sync(0xFFFFFFFFu, inc, d);
        if (lane >= d) inc += u;
    }
    if (lane == 31) wsum[w] = inc;
    __syncthreads();
    if (w == 0) {
        int x = wsum[lane];
        #pragma unroll
        for (int d = 1; d < 32; d <<= 1) {
            int u = __shfl_up_sync(0xFFFFFFFFu, x, d);
            if (lane >= d) x += u;
        }
        wsum[lane] = x;
    }
    __syncthreads();
    int excl = inc - v + (w ? wsum[w - 1] : 0);
    if (i < n) g_rowptr[i] = excl;
    if (t == 1023) g_bsum[blockIdx.x] = excl + v;
}

__global__ void scan2_kernel(int nb) {
    __shared__ int wsum[32];
    int t = threadIdx.x;                     // 1024 threads
    int v = (t < nb) ? g_bsum[t] : 0;
    int lane = t & 31, w = t >> 5;
    int inc = v;
    #pragma unroll
    for (int d = 1; d < 32; d <<= 1) {
        int u = __shfl_up_sync(0xFFFFFFFFu, inc, d);
        if (lane >= d) inc += u;
    }
    if (lane == 31) wsum[w] = inc;
    __syncthreads();
    if (w == 0) {
        int x = wsum[lane];
        #pragma unroll
        for (int d = 1; d < 32; d <<= 1) {
            int u = __shfl_up_sync(0xFFFFFFFFu, x, d);
            if (lane >= d) x += u;
        }
        wsum[lane] = x;
    }
    __syncthreads();
    int excl = inc - v + (w ? wsum[w - 1] : 0);
    if (t < nb) g_bsum[t] = excl;
}

__global__ void scan3_kernel(int n) {
    int i = blockIdx.x * blockDim.x + threadIdx.x;
    if (i >= n) return;
    int d = g_degi[i];
    int r = g_rowptr[i] + g_bsum[i >> 10];
    g_rowptr[i] = r;
    g_cursor[i] = r;
    g_dinv[i] = rsqrtf((float)d + 1.f);
    if (i == n - 1) g_rowptr[n] = r + d;
}

__global__ void place_kernel(const void* __restrict__ ei, int E) {
    int e = blockIdx.x * blockDim.x + threadIdx.x;
    if (e >= E) return;
    int is64 = g_is64;
    int src = load_idx(ei, e, is64);
    int dst = load_idx(ei, (long long)E + e, is64);
    int pos = atomicAdd(&g_cursor[dst], 1);
    g_elist[pos] = src;
}

// ---------------------------------------------------------------------------
// A = bf16(x * dinv[row]), rows >= n zero-padded
__global__ void convert_kernel(const float* __restrict__ x, int n) {
    long long idx = (long long)blockIdx.x * blockDim.x + threadIdx.x;
    if (idx >= (long long)NODES_PAD * 128) return;
    int row = (int)(idx >> 7);
    int p = (int)(idx & 127);
    int c = p * 2;
    float v0 = 0.f, v1 = 0.f;
    if (row < n) {
        float d = g_dinv[row];
        v0 = x[(size_t)row * C + c] * d;
        v1 = x[(size_t)row * C + c + 1] * d;
    }
    __nv_bfloat162 hi2 = __float22bfloat162_rn(make_float2(v0, v1));
    ((__nv_bfloat162*)(g_A + (size_t)row * C))[p] = hi2;
}

// B rows nn: bf16(W1[:, nn]), K-major [nn][k]
__global__ void bbuild_kernel(const float* __restrict__ W1) {
    int idx = blockIdx.x * blockDim.x + threadIdx.x;
    if (idx >= C * C) return;
    int nn = idx >> 8, k = idx & 255;
    g_B[(size_t)nn * C + k] = __float2bfloat16(W1[(size_t)k * C + nn]);
}

// ---------------------------------------------------------------------------
// bf16 mma.sync GEMM, K=256, cp.async double buffered; epilogue packs bf16x2.
#define APAD 72
#define STG_ELEMS ((128 + 256) * APAD)

__device__ __forceinline__ void load_stage(uint32_t sbase, int tid, int m0,
                                           int kc, int s) {
    uint32_t As = sbase + (uint32_t)(s * STG_ELEMS) * 2;
    uint32_t Bs = As + 128 * APAD * 2;
    const __nv_bfloat16* Ab = g_A + (size_t)m0 * C + kc * 64;
    #pragma unroll
    for (int i = 0; i < 4; i++) {
        int u = tid + i * 256;
        int r = u >> 3, o = u & 7;
        cp16(As + (uint32_t)(r * APAD + o * 8) * 2,
             Ab + (size_t)r * C + o * 8);
    }
    const __nv_bfloat16* Bb = g_B + kc * 64;
    #pragma unroll
    for (int i = 0; i < 8; i++) {
        int u = tid + i * 256;
        int r = u >> 3, o = u & 7;
        cp16(Bs + (uint32_t)(r * APAD + o * 8) * 2,
             Bb + (size_t)r * C + o * 8);
    }
    CP_COMMIT();
}

__global__ void __launch_bounds__(256) gemm_mma_kernel() {
    extern __shared__ __nv_bfloat16 smem[];

    int tid = threadIdx.x;
    int wid = tid >> 5, lane = tid & 31;
    int g = lane >> 2, tir = lane & 3;
    int wm = wid & 1, wn = wid >> 1;          // warp grid 2 x 4
    int m0 = blockIdx.x * 128;

    uint32_t sbase = smem_u32(smem);
    const int NKC = C / 64;                   // 4 chunks

    float c[4][8][4];
    #pragma unroll
    for (int mt = 0; mt < 4; mt++)
        #pragma unroll
        for (int nt = 0; nt < 8; nt++)
            #pragma unroll
            for (int q = 0; q < 4; q++) c[mt][nt][q] = 0.f;

    load_stage(sbase, tid, m0, 0, 0);

    for (int kc = 0; kc < NKC; kc++) {
        if (kc + 1 < NKC) {
            load_stage(sbase, tid, m0, kc + 1, (kc + 1) & 1);
            CP_WAIT(1);
        } else {
            CP_WAIT(0);
        }
        __syncthreads();

        const __nv_bfloat16* As = smem + (kc & 1) * STG_ELEMS;
        const __nv_bfloat16* Bs = As + 128 * APAD;

        #pragma unroll
        for (int ks = 0; ks < 4; ks++) {
            int kof = ks * 16 + tir * 2;
            uint32_t a[4][4];
            #pragma unroll
            for (int mt = 0; mt < 4; mt++) {
                int base = (wm * 64 + mt * 16 + g) * APAD + kof;
                a[mt][0] = *(const uint32_t*)(As + base);
                a[mt][1] = *(const uint32_t*)(As + base + 8 * APAD);
                a[mt][2] = *(const uint32_t*)(As + base + 8);
                a[mt][3] = *(const uint32_t*)(As + base + 8 * APAD + 8);
            }
            uint32_t b[8][2];
            #pragma unroll
            for (int nt = 0; nt < 8; nt++) {
                int base = (wn * 64 + nt * 8 + g) * APAD + kof;
                b[nt][0] = *(const uint32_t*)(Bs + base);
                b[nt][1] = *(const uint32_t*)(Bs + base + 8);
            }
            #pragma unroll
            for (int mt = 0; mt < 4; mt++)
                #pragma unroll
                for (int nt = 0; nt < 8; nt++)
                    mma16816(c[mt][nt], a[mt], b[nt]);
        }
        __syncthreads();
    }

    // epilogue: pack fp32 pair -> bf16x2, single 4B store per fragment half
    #pragma unroll
    for (int mt = 0; mt < 4; mt++) {
        int row = m0 + wm * 64 + mt * 16 + g;
        #pragma unroll
        for (int nt = 0; nt < 8; nt++) {
            int col2 = wn * 32 + nt * 4 + tir;   // (col)/2, col even
            __nv_bfloat162 p0 = __float22bfloat162_rn(
                make_float2(c[mt][nt][0], c[mt][nt][1]));
            __nv_bfloat162 p1 = __float22bfloat162_rn(
                make_float2(c[mt][nt][2], c[mt][nt][3]));
            g_hsb[(size_t)row * (C / 2) + col2]       = *(uint32_t*)&p0;
            g_hsb[(size_t)(row + 8) * (C / 2) + col2] = *(uint32_t*)&p1;
        }
    }
}

// ---------------------------------------------------------------------------
// fused CSR gather + relu + sorted-run mean-pool, uint4-wide (warp per row).
// Block = 128 threads = 4 node lanes x 32 threads. Thread (w, q) owns uint4
// word q of its lane's rows = channels 8q..8q+7; one LDG.128 covers a full
// 512B row per warp. Lane w processes nodes start+w, start+w+4, ...
// 4 nodes in flight per block; LDG issue count halved again vs uint2.
#define NPB 64
__global__ void __launch_bounds__(128) gather_pool_kernel(
        const void* __restrict__ batch, const float* __restrict__ b1, int n) {
    int t = threadIdx.x;
    int w = t >> 5;                      // node lane 0..3
    int q = t & 31;                      // uint4 word; channels 8q..8q+7
    int start = blockIdx.x * NPB;
    if (start >= n) return;
    int end = min(start + NPB, n);
    int is64 = g_is64;

    float bias[8];
    *(float4*)&bias[0] = *(const float4*)(b1 + 8 * q);
    *(float4*)&bias[4] = *(const float4*)(b1 + 8 * q + 4);

    int first = start + w;
    if (first >= end) return;
    int gp = load_idx(batch, first, is64);
    float acc[8] = {0.f, 0.f, 0.f, 0.f, 0.f, 0.f, 0.f, 0.f};

    for (int i = first; i < end; i += 4) {
        int gid = load_idx(batch, i, is64);
        if (gid != gp) {
            #pragma unroll
            for (int k = 0; k < 8; k++)
                atomicAdd(&g_sums[gp * C + 8 * q + k], acc[k]);
            #pragma unroll
            for (int k = 0; k < 8; k++) acc[k] = 0.f;
            gp = gid;
        }

        int r0 = g_rowptr[i], r1 = g_rowptr[i + 1];
        const uint4* rowp = (const uint4*)(g_hsb + (size_t)i * 128);
        uint4 wv = rowp[q];                              // self-loop
        float s[8], u[8];
        {
            float2 f0 = __bfloat1622float2(*(__nv_bfloat162*)&wv.x);
            float2 f1 = __bfloat1622float2(*(__nv_bfloat162*)&wv.y);
            float2 f2 = __bfloat1622float2(*(__nv_bfloat162*)&wv.z);
            float2 f3 = __bfloat1622float2(*(__nv_bfloat162*)&wv.w);
            s[0] = f0.x; s[1] = f0.y; s[2] = f1.x; s[3] = f1.y;
            s[4] = f2.x; s[5] = f2.y; s[6] = f3.x; s[7] = f3.y;
            #pragma unroll
            for (int k = 0; k < 8; k++) u[k] = 0.f;
        }

        int j = r0;
        for (; j + 4 <= r1; j += 4) {
            int e0 = g_elist[j],     e1 = g_elist[j + 1];
            int e2 = g_elist[j + 2], e3 = g_elist[j + 3];
            uint4 w0 = ((const uint4*)(g_hsb + (size_t)e0 * 128))[q];
            uint4 w1 = ((const uint4*)(g_hsb + (size_t)e1 * 128))[q];
            uint4 w2 = ((const uint4*)(g_hsb + (size_t)e2 * 128))[q];
            uint4 w3 = ((const uint4*)(g_hsb + (size_t)e3 * 128))[q];
            {
                float2 a0 = __bfloat1622float2(*(__nv_bfloat162*)&w0.x);
                float2 a1 = __bfloat1622float2(*(__nv_bfloat162*)&w0.y);
                float2 a2 = __bfloat1622float2(*(__nv_bfloat162*)&w0.z);
                float2 a3 = __bfloat1622float2(*(__nv_bfloat162*)&w0.w);
                s[0] += a0.x; s[1] += a0.y; s[2] += a1.x; s[3] += a1.y;
                s[4] += a2.x; s[5] += a2.y; s[6] += a3.x; s[7] += a3.y;
            }
            {
                float2 a0 = __bfloat1622float2(*(__nv_bfloat162*)&w1.x);
                float2 a1 = __bfloat1622float2(*(__nv_bfloat162*)&w1.y);
                float2 a2 = __bfloat1622float2(*(__nv_bfloat162*)&w1.z);
                float2 a3 = __bfloat1622float2(*(__nv_bfloat162*)&w1.w);
                u[0] += a0.x; u[1] += a0.y; u[2] += a1.x; u[3] += a1.y;
                u[4] += a2.x; u[5] += a2.y; u[6] += a3.x; u[7] += a3.y;
            }
            {
                float2 a0 = __bfloat1622float2(*(__nv_bfloat162*)&w2.x);
                float2 a1 = __bfloat1622float2(*(__nv_bfloat162*)&w2.y);
                float2 a2 = __bfloat1622float2(*(__nv_bfloat162*)&w2.z);
                float2 a3 = __bfloat1622float2(*(__nv_bfloat162*)&w2.w);
                s[0] += a0.x; s[1] += a0.y; s[2] += a1.x; s[3] += a1.y;
                s[4] += a2.x; s[5] += a2.y; s[6] += a3.x; s[7] += a3.y;
            }
            {
                float2 a0 = __bfloat1622float2(*(__nv_bfloat162*)&w3.x);
                float2 a1 = __bfloat1622float2(*(__nv_bfloat162*)&w3.y);
                float2 a2 = __bfloat1622float2(*(__nv_bfloat162*)&w3.z);
                float2 a3 = __bfloat1622float2(*(__nv_bfloat162*)&w3.w);
                u[0] += a0.x; u[1] += a0.y; u[2] += a1.x; u[3] += a1.y;
                u[4] += a2.x; u[5] += a2.y; u[6] += a3.x; u[7] += a3.y;
            }
        }
        for (; j < r1; j++) {
            uint4 wj = ((const uint4*)(g_hsb + (size_t)g_elist[j] * 128))[q];
            float2 a0 = __bfloat1622float2(*(__nv_bfloat162*)&wj.x);
            float2 a1 = __bfloat1622float2(*(__nv_bfloat162*)&wj.y);
            float2 a2 = __bfloat1622float2(*(__nv_bfloat162*)&wj.z);
            float2 a3 = __bfloat1622float2(*(__nv_bfloat162*)&wj.w);
            s[0] += a0.x; s[1] += a0.y; s[2] += a1.x; s[3] += a1.y;
            s[4] += a2.x; s[5] += a2.y; s[6] += a3.x; s[7] += a3.y;
        }

        float di = g_dinv[i];
        #pragma unroll
        for (int k = 0; k < 8; k++)
            acc[k] += fmaxf(di * (s[k] + u[k]) + bias[k], 0.f);
    }
    #pragma unroll
    for (int k = 0; k < 8; k++)
        atomicAdd(&g_sums[gp * C + 8 * q + k], acc[k]);
}

// ---------------------------------------------------------------------------
// counts: register run-length accumulation, one thread per 64 nodes
__global__ void bcount_kernel(const void* __restrict__ batch, int n) {
    int seg = (blockIdx.x * blockDim.x + threadIdx.x);
    int start = seg * 64;
    if (start >= n) return;
    int end = min(start + 64, n);
    int is64 = g_is64;
    int gp = load_idx(batch, start, is64);
    float cnt = 0.f;
    for (int i = start; i < end; i++) {
        int g = load_idx(batch, i, is64);
        if (g != gp) { atomicAdd(&g_counts[gp], cnt); cnt = 0.f; gp = g; }
        cnt += 1.f;
    }
    atomicAdd(&g_counts[gp], cnt);
}

__global__ void final_kernel(const float* __restrict__ W2,
                             const float* __restrict__ b2,
                             float* __restrict__ out) {
    int t = threadIdx.x;
    if (t >= GRAPHS * OUTC) return;
    int g = t / OUTC, o = t % OUTC;
    float s = 0.f;
    #pragma unroll 8
    for (int k = 0; k < C; k++)
        s += g_sums[g * C + k] * W2[k * OUTC + o];
    out[t] = s / fmaxf(g_counts[g], 1.f) + b2[o];
}

// ---------------------------------------------------------------------------
extern "C" void kernel_launch(void* const* d_in, const int* in_sizes, int n_in,
                              void* d_out, int out_size) {
    const float* x     = (const float*)d_in[0];
    const void*  ei    = d_in[1];
    const void*  batch = d_in[2];
    const float* W1    = (const float*)d_in[3];
    const float* b1    = (const float*)d_in[4];
    const float* W2    = (const float*)d_in[5];
    const float* b2    = (const float*)d_in[6];
    float* out = (float*)d_out;

    int n = in_sizes[0] / C;    // 100000
    int E = in_sizes[1] / 2;    // 1600000
    int nb = (n + 1023) / 1024;

    detect_kernel<<<1, 32>>>((const int*)ei);
    init_kernel<<<(n + 255) / 256, 256>>>(n);
    degi_kernel<<<(E + 255) / 256, 256>>>(ei, E);
    scan1_kernel<<<nb, 1024>>>(n);
    scan2_kernel<<<1, 1024>>>(nb);
    scan3_kernel<<<(n + 255) / 256, 256>>>(n);

    convert_kernel<<<(NODES_PAD * 128 + 255) / 256, 256>>>(x, n);
    bbuild_kernel<<<256, 256>>>(W1);

    static const int SMEM_BYTES = 2 * STG_ELEMS * 2;   // 110592
    cudaFuncSetAttribute(gemm_mma_kernel,
                         cudaFuncAttributeMaxDynamicSharedMemorySize, SMEM_BYTES);
    gemm_mma_kernel<<<NODES_PAD / 128, 256, SMEM_BYTES>>>();

    place_kernel<<<(E + 255) / 256, 256>>>(ei, E);
    bcount_kernel<<<(n / 64 + 255) / 256, 256>>>(batch, n);
    gather_pool_kernel<<<(n + NPB - 1) / NPB, 128>>>(batch, b1, n);
    final_kernel<<<1, 640>>>(W2, b2, out);
}

// round 14
// speedup vs baseline: 1.0483x; 1.0483x over previous
#include <cuda_runtime.h>
#include <cuda_bf16.h>
#include <cstdint>

#define NODES    100000
#define NODES_PAD 100096          // 782 * 128
#define C        256
#define GRAPHS   64
#define OUTC     10
#define EMAX     1600000
#define NB1024   ((NODES + 1023) / 1024)

// ---------------- scratch (static device globals; no allocation) ----------
__device__ __align__(16) __nv_bfloat16 g_A[(size_t)NODES_PAD * C];  // bf16(x*dinv)
__device__ __align__(16) __nv_bfloat16 g_B[(size_t)C * C];          // bf16(W1^T)
__device__ __align__(16) uint32_t g_hsb[(size_t)NODES_PAD * (C / 2)]; // bf16x2
__device__ float g_dinv[NODES];
__device__ int   g_degi[NODES];
__device__ int   g_rowptr[NODES + 1];
__device__ int   g_cursor[NODES];
__device__ int   g_elist[EMAX];
__device__ int   g_bsum[NB1024 + 1];
__device__ float g_sums[GRAPHS * C];
__device__ float g_counts[GRAPHS];
__device__ int   g_is64;

// ---------------- helpers ------------------------------------------------
__device__ __forceinline__ int load_idx(const void* p, long long i, int is64) {
    if (is64) return (int)((const long long*)p)[i];
    return ((const int*)p)[i];
}

__device__ __forceinline__ void mma16816(float* c, const uint32_t* a,
                                         const uint32_t* b) {
    asm volatile(
        "mma.sync.aligned.m16n8k16.row.col.f32.bf16.bf16.f32 "
        "{%0,%1,%2,%3}, {%4,%5,%6,%7}, {%8,%9}, {%0,%1,%2,%3};"
        : "+f"(c[0]), "+f"(c[1]), "+f"(c[2]), "+f"(c[3])
        : "r"(a[0]), "r"(a[1]), "r"(a[2]), "r"(a[3]), "r"(b[0]), "r"(b[1]));
}

__device__ __forceinline__ uint32_t smem_u32(const void* p) {
    uint32_t a;
    asm("{ .reg .u64 t; cvta.to.shared.u64 t, %1; cvt.u32.u64 %0, t; }"
        : "=r"(a) : "l"(p));
    return a;
}
__device__ __forceinline__ void cp16(uint32_t dst, const void* src) {
    asm volatile("cp.async.ca.shared.global [%0], [%1], 16;"
                 :: "r"(dst), "l"(src) : "memory");
}
#define CP_COMMIT() asm volatile("cp.async.commit_group;" ::: "memory")
#define CP_WAIT(N)  asm volatile("cp.async.wait_group %0;" :: "n"(N) : "memory")

// ---------------------------------------------------------------------------
__global__ void detect_kernel(const int* __restrict__ ei32) {
    if (threadIdx.x == 0 && blockIdx.x == 0) {
        int nz = 0;
        #pragma unroll
        for (int i = 1; i < 256; i += 2) nz |= (ei32[i] != 0);
        g_is64 = (nz == 0) ? 1 : 0;
    }
}

__global__ void init_kernel(int n) {
    int i = blockIdx.x * blockDim.x + threadIdx.x;
    if (i < n) g_degi[i] = 0;
    if (i < GRAPHS * C) g_sums[i] = 0.f;
    if (i < GRAPHS) g_counts[i] = 0.f;
}

__global__ void degi_kernel(const void* __restrict__ ei, int E) {
    int i = blockIdx.x * blockDim.x + threadIdx.x;
    if (i >= E) return;
    int d = load_idx(ei, (long long)E + i, g_is64);
    atomicAdd(&g_degi[d], 1);
}

// ---------------- hierarchical scan ----------------------------------------
__global__ void scan1_kernel(int n) {
    __shared__ int wsum[32];
    int t = threadIdx.x;
    int i = blockIdx.x * 1024 + t;
    int v = (i < n) ? g_degi[i] : 0;
    int lane = t & 31, w = t >> 5;
    int inc = v;
    #pragma unroll
    for (int d = 1; d < 32; d <<= 1) {
        int u = __shfl_up_sync(0xFFFFFFFFu, inc, d);
        if (lane >= d) inc += u;
    }
    if (lane == 31) wsum[w] = inc;
    __syncthreads();
    if (w == 0) {
        int x = wsum[lane];
        #pragma unroll
        for (int d = 1; d < 32; d <<= 1) {
            int u = __shfl_up_sync(0xFFFFFFFFu, x, d);
            if (lane >= d) x += u;
        }
        wsum[lane] = x;
    }
    __syncthreads();
    int excl = inc - v + (w ? wsum[w - 1] : 0);
    if (i < n) g_rowptr[i] = excl;
    if (t == 1023) g_bsum[blockIdx.x] = excl + v;
}

__global__ void scan2_kernel(int nb) {
    __shared__ int wsum[32];
    int t = threadIdx.x;                     // 1024 threads
    int v = (t < nb) ? g_bsum[t] : 0;
    int lane = t & 31, w = t >> 5;
    int inc = v;
    #pragma unroll
    for (int d = 1; d < 32; d <<= 1) {
        int u = __shfl_up_sync(0xFFFFFFFFu, inc, d);
        if (lane >= d) inc += u;
    }
    if (lane == 31) wsum[w] = inc;
    __syncthreads();
    if (w == 0) {
        int x = wsum[lane];
        #pragma unroll
        for (int d = 1; d < 32; d <<= 1) {
            int u = __shfl_up_sync(0xFFFFFFFFu, x, d);
            if (lane >= d) x += u;
        }
        wsum[lane] = x;
    }
    __syncthreads();
    int excl = inc - v + (w ? wsum[w - 1] : 0);
    if (t < nb) g_bsum[t] = excl;
}

__global__ void scan3_kernel(int n) {
    int i = blockIdx.x * blockDim.x + threadIdx.x;
    if (i >= n) return;
    int d = g_degi[i];
    int r = g_rowptr[i] + g_bsum[i >> 10];
    g_rowptr[i] = r;
    g_cursor[i] = r;
    g_dinv[i] = rsqrtf((float)d + 1.f);
    if (i == n - 1) g_rowptr[n] = r + d;
}

__global__ void place_kernel(const void* __restrict__ ei, int E) {
    int e = blockIdx.x * blockDim.x + threadIdx.x;
    if (e >= E) return;
    int is64 = g_is64;
    int src = load_idx(ei, e, is64);
    int dst = load_idx(ei, (long long)E + e, is64);
    int pos = atomicAdd(&g_cursor[dst], 1);
    g_elist[pos] = src;
}

// ---------------------------------------------------------------------------
// A = bf16(x * dinv[row]), rows >= n zero-padded
__global__ void convert_kernel(const float* __restrict__ x, int n) {
    long long idx = (long long)blockIdx.x * blockDim.x + threadIdx.x;
    if (idx >= (long long)NODES_PAD * 128) return;
    int row = (int)(idx >> 7);
    int p = (int)(idx & 127);
    int c = p * 2;
    float v0 = 0.f, v1 = 0.f;
    if (row < n) {
        float d = g_dinv[row];
        v0 = x[(size_t)row * C + c] * d;
        v1 = x[(size_t)row * C + c + 1] * d;
    }
    __nv_bfloat162 hi2 = __float22bfloat162_rn(make_float2(v0, v1));
    ((__nv_bfloat162*)(g_A + (size_t)row * C))[p] = hi2;
}

// B rows nn: bf16(W1[:, nn]), K-major [nn][k]
__global__ void bbuild_kernel(const float* __restrict__ W1) {
    int idx = blockIdx.x * blockDim.x + threadIdx.x;
    if (idx >= C * C) return;
    int nn = idx >> 8, k = idx & 255;
    g_B[(size_t)nn * C + k] = __float2bfloat16(W1[(size_t)k * C + nn]);
}

// ---------------------------------------------------------------------------
// bf16 mma.sync GEMM, K=256, cp.async double buffered; epilogue packs bf16x2.
#define APAD 72
#define STG_ELEMS ((128 + 256) * APAD)

__device__ __forceinline__ void load_stage(uint32_t sbase, int tid, int m0,
                                           int kc, int s) {
    uint32_t As = sbase + (uint32_t)(s * STG_ELEMS) * 2;
    uint32_t Bs = As + 128 * APAD * 2;
    const __nv_bfloat16* Ab = g_A + (size_t)m0 * C + kc * 64;
    #pragma unroll
    for (int i = 0; i < 4; i++) {
        int u = tid + i * 256;
        int r = u >> 3, o = u & 7;
        cp16(As + (uint32_t)(r * APAD + o * 8) * 2,
             Ab + (size_t)r * C + o * 8);
    }
    const __nv_bfloat16* Bb = g_B + kc * 64;
    #pragma unroll
    for (int i = 0; i < 8; i++) {
        int u = tid + i * 256;
        int r = u >> 3, o = u & 7;
        cp16(Bs + (uint32_t)(r * APAD + o * 8) * 2,
             Bb + (size_t)r * C + o * 8);
    }
    CP_COMMIT();
}

__global__ void __launch_bounds__(256) gemm_mma_kernel() {
    extern __shared__ __nv_bfloat16 smem[];

    int tid = threadIdx.x;
    int wid = tid >> 5, lane = tid & 31;
    int g = lane >> 2, tir = lane & 3;
    int wm = wid & 1, wn = wid >> 1;          // warp grid 2 x 4
    int m0 = blockIdx.x * 128;

    uint32_t sbase = smem_u32(smem);
    const int NKC = C / 64;                   // 4 chunks

    float c[4][8][4];
    #pragma unroll
    for (int mt = 0; mt < 4; mt++)
        #pragma unroll
        for (int nt = 0; nt < 8; nt++)
            #pragma unroll
            for (int q = 0; q < 4; q++) c[mt][nt][q] = 0.f;

    load_stage(sbase, tid, m0, 0, 0);

    for (int kc = 0; kc < NKC; kc++) {
        if (kc + 1 < NKC) {
            load_stage(sbase, tid, m0, kc + 1, (kc + 1) & 1);
            CP_WAIT(1);
        } else {
            CP_WAIT(0);
        }
        __syncthreads();

        const __nv_bfloat16* As = smem + (kc & 1) * STG_ELEMS;
        const __nv_bfloat16* Bs = As + 128 * APAD;

        #pragma unroll
        for (int ks = 0; ks < 4; ks++) {
            int kof = ks * 16 + tir * 2;
            uint32_t a[4][4];
            #pragma unroll
            for (int mt = 0; mt < 4; mt++) {
                int base = (wm * 64 + mt * 16 + g) * APAD + kof;
                a[mt][0] = *(const uint32_t*)(As + base);
                a[mt][1] = *(const uint32_t*)(As + base + 8 * APAD);
                a[mt][2] = *(const uint32_t*)(As + base + 8);
                a[mt][3] = *(const uint32_t*)(As + base + 8 * APAD + 8);
            }
            uint32_t b[8][2];
            #pragma unroll
            for (int nt = 0; nt < 8; nt++) {
                int base = (wn * 64 + nt * 8 + g) * APAD + kof;
                b[nt][0] = *(const uint32_t*)(Bs + base);
                b[nt][1] = *(const uint32_t*)(Bs + base + 8);
            }
            #pragma unroll
            for (int mt = 0; mt < 4; mt++)
                #pragma unroll
                for (int nt = 0; nt < 8; nt++)
                    mma16816(c[mt][nt], a[mt], b[nt]);
        }
        __syncthreads();
    }

    // epilogue: pack fp32 pair -> bf16x2, single 4B store per fragment half
    #pragma unroll
    for (int mt = 0; mt < 4; mt++) {
        int row = m0 + wm * 64 + mt * 16 + g;
        #pragma unroll
        for (int nt = 0; nt < 8; nt++) {
            int col2 = wn * 32 + nt * 4 + tir;   // (col)/2, col even
            __nv_bfloat162 p0 = __float22bfloat162_rn(
                make_float2(c[mt][nt][0], c[mt][nt][1]));
            __nv_bfloat162 p1 = __float22bfloat162_rn(
                make_float2(c[mt][nt][2], c[mt][nt][3]));
            g_hsb[(size_t)row * (C / 2) + col2]       = *(uint32_t*)&p0;
            g_hsb[(size_t)(row + 8) * (C / 2) + col2] = *(uint32_t*)&p1;
        }
    }
}

// ---------------------------------------------------------------------------
// fused CSR gather + relu + sorted-run mean-pool, uint2-wide (R12 shape).
// Block = 128 threads in two halves: half h (64 threads) processes nodes
// start+h, start+h+2, ... Each thread owns one uint2 word = 4 channels, so
// 64 threads cover a full 512B row; a warp reads 256B (2 lines) per LDG.
// NPB=32: 3125 blocks for better latency hiding / tail balance.
#define NPB 32
__global__ void __launch_bounds__(128) gather_pool_kernel(
        const void* __restrict__ batch, const float* __restrict__ b1, int n) {
    int t = threadIdx.x;
    int h = t >> 6;                      // node-parity half
    int q = t & 63;                      // uint2 word index; channels 4q..4q+3
    int start = blockIdx.x * NPB;
    if (start >= n) return;
    int end = min(start + NPB, n);
    int is64 = g_is64;

    float b0 = b1[4 * q + 0], bq1 = b1[4 * q + 1];
    float b2v = b1[4 * q + 2], b3v = b1[4 * q + 3];

    int first = start + h;
    if (first >= end) return;
    int gp = load_idx(batch, first, is64);
    float acc0 = 0.f, acc1 = 0.f, acc2 = 0.f, acc3 = 0.f;

    for (int i = first; i < end; i += 2) {
        int gid = load_idx(batch, i, is64);
        if (gid != gp) {
            atomicAdd(&g_sums[gp * C + 4 * q + 0], acc0);
            atomicAdd(&g_sums[gp * C + 4 * q + 1], acc1);
            atomicAdd(&g_sums[gp * C + 4 * q + 2], acc2);
            atomicAdd(&g_sums[gp * C + 4 * q + 3], acc3);
            acc0 = acc1 = acc2 = acc3 = 0.f;
            gp = gid;
        }

        int r0 = g_rowptr[i], r1 = g_rowptr[i + 1];
        uint2 w = ((const uint2*)(g_hsb + (size_t)i * 128))[q];   // self-loop
        float2 fa = __bfloat1622float2(*(__nv_bfloat162*)&w.x);
        float2 fb = __bfloat1622float2(*(__nv_bfloat162*)&w.y);
        float s0 = fa.x, s1 = fa.y, s2 = fb.x, s3 = fb.y;
        float u0 = 0.f, u1 = 0.f, u2 = 0.f, u3 = 0.f;

        int j = r0;
        for (; j + 4 <= r1; j += 4) {
            int e0 = g_elist[j],     e1 = g_elist[j + 1];
            int e2 = g_elist[j + 2], e3 = g_elist[j + 3];
            uint2 w0 = ((const uint2*)(g_hsb + (size_t)e0 * 128))[q];
            uint2 w1 = ((const uint2*)(g_hsb + (size_t)e1 * 128))[q];
            uint2 w2 = ((const uint2*)(g_hsb + (size_t)e2 * 128))[q];
            uint2 w3 = ((const uint2*)(g_hsb + (size_t)e3 * 128))[q];
            float2 a0 = __bfloat1622float2(*(__nv_bfloat162*)&w0.x);
            float2 a1 = __bfloat1622float2(*(__nv_bfloat162*)&w0.y);
            float2 c0 = __bfloat1622float2(*(__nv_bfloat162*)&w1.x);
            float2 c1 = __bfloat1622float2(*(__nv_bfloat162*)&w1.y);
            float2 d0 = __bfloat1622float2(*(__nv_bfloat162*)&w2.x);
            float2 d1 = __bfloat1622float2(*(__nv_bfloat162*)&w2.y);
            float2 e0f = __bfloat1622float2(*(__nv_bfloat162*)&w3.x);
            float2 e1f = __bfloat1622float2(*(__nv_bfloat162*)&w3.y);
            s0 += a0.x + d0.x; s1 += a0.y + d0.y;
            s2 += a1.x + d1.x; s3 += a1.y + d1.y;
            u0 += c0.x + e0f.x; u1 += c0.y + e0f.y;
            u2 += c1.x + e1f.x; u3 += c1.y + e1f.y;
        }
        for (; j < r1; j++) {
            uint2 wj = ((const uint2*)(g_hsb + (size_t)g_elist[j] * 128))[q];
            float2 a0 = __bfloat1622float2(*(__nv_bfloat162*)&wj.x);
            float2 a1 = __bfloat1622float2(*(__nv_bfloat162*)&wj.y);
            s0 += a0.x; s1 += a0.y; s2 += a1.x; s3 += a1.y;
        }

        float di = g_dinv[i];
        acc0 += fmaxf(di * (s0 + u0) + b0, 0.f);
        acc1 += fmaxf(di * (s1 + u1) + bq1, 0.f);
        acc2 += fmaxf(di * (s2 + u2) + b2v, 0.f);
        acc3 += fmaxf(di * (s3 + u3) + b3v, 0.f);
    }
    atomicAdd(&g_sums[gp * C + 4 * q + 0], acc0);
    atomicAdd(&g_sums[gp * C + 4 * q + 1], acc1);
    atomicAdd(&g_sums[gp * C + 4 * q + 2], acc2);
    atomicAdd(&g_sums[gp * C + 4 * q + 3], acc3);
}

// ---------------------------------------------------------------------------
// counts: register run-length accumulation, one thread per 64 nodes
__global__ void bcount_kernel(const void* __restrict__ batch, int n) {
    int seg = (blockIdx.x * blockDim.x + threadIdx.x);
    int start = seg * 64;
    if (start >= n) return;
    int end = min(start + 64, n);
    int is64 = g_is64;
    int gp = load_idx(batch, start, is64);
    float cnt = 0.f;
    for (int i = start; i < end; i++) {
        int g = load_idx(batch, i, is64);
        if (g != gp) { atomicAdd(&g_counts[gp], cnt); cnt = 0.f; gp = g; }
        cnt += 1.f;
    }
    atomicAdd(&g_counts[gp], cnt);
}

__global__ void final_kernel(const float* __restrict__ W2,
                             const float* __restrict__ b2,
                             float* __restrict__ out) {
    int t = threadIdx.x;
    if (t >= GRAPHS * OUTC) return;
    int g = t / OUTC, o = t % OUTC;
    float s = 0.f;
    #pragma unroll 8
    for (int k = 0; k < C; k++)
        s += g_sums[g * C + k] * W2[k * OUTC + o];
    out[t] = s / fmaxf(g_counts[g], 1.f) + b2[o];
}

// ---------------------------------------------------------------------------
extern "C" void kernel_launch(void* const* d_in, const int* in_sizes, int n_in,
                              void* d_out, int out_size) {
    const float* x     = (const float*)d_in[0];
    const void*  ei    = d_in[1];
    const void*  batch = d_in[2];
    const float* W1    = (const float*)d_in[3];
    const float* b1    = (const float*)d_in[4];
    const float* W2    = (const float*)d_in[5];
    const float* b2    = (const float*)d_in[6];
    float* out = (float*)d_out;

    int n = in_sizes[0] / C;    // 100000
    int E = in_sizes[1] / 2;    // 1600000
    int nb = (n + 1023) / 1024;

    detect_kernel<<<1, 32>>>((const int*)ei);
    init_kernel<<<(n + 255) / 256, 256>>>(n);
    degi_kernel<<<(E + 255) / 256, 256>>>(ei, E);
    scan1_kernel<<<nb, 1024>>>(n);
    scan2_kernel<<<1, 1024>>>(nb);
    scan3_kernel<<<(n + 255) / 256, 256>>>(n);

    convert_kernel<<<(NODES_PAD * 128 + 255) / 256, 256>>>(x, n);
    bbuild_kernel<<<256, 256>>>(W1);

    static const int SMEM_BYTES = 2 * STG_ELEMS * 2;   // 110592
    cudaFuncSetAttribute(gemm_mma_kernel,
                         cudaFuncAttributeMaxDynamicSharedMemorySize, SMEM_BYTES);
    gemm_mma_kernel<<<NODES_PAD / 128, 256, SMEM_BYTES>>>();

    place_kernel<<<(E + 255) / 256, 256>>>(ei, E);
    bcount_kernel<<<(n / 64 + 255) / 256, 256>>>(batch, n);
    gather_pool_kernel<<<(n + NPB - 1) / NPB, 128>>>(batch, b1, n);
    final_kernel<<<1, 640>>>(W2, b2, out);
}

// round 15
// speedup vs baseline: 1.1536x; 1.1005x over previous
#include <cuda_runtime.h>
#include <cuda_bf16.h>
#include <cstdint>

#define NODES    100000
#define NODES_PAD 100096          // 782 * 128
#define C        256
#define GRAPHS   64
#define OUTC     10
#define EMAX     1600000
#define NB1024   ((NODES + 1023) / 1024)

// ---------------- scratch (static device globals; no allocation) ----------
__device__ __align__(16) __nv_bfloat16 g_A[(size_t)NODES_PAD * C];  // bf16(x*dinv)
__device__ __align__(16) __nv_bfloat16 g_B[(size_t)C * C];          // bf16(W1^T)
__device__ __align__(16) uint32_t g_hsb[(size_t)NODES_PAD * (C / 2)]; // bf16x2
__device__ float g_dinv[NODES];
__device__ int   g_degi[NODES];
__device__ int   g_rowptr[NODES + 1];
__device__ int   g_cursor[NODES];
__device__ int   g_elist[EMAX];
__device__ int   g_bsum[NB1024 + 1];
__device__ float g_sums[GRAPHS * C];
__device__ float g_counts[GRAPHS];
__device__ int   g_is64;

// ---------------- helpers ------------------------------------------------
__device__ __forceinline__ int load_idx(const void* p, long long i, int is64) {
    if (is64) return (int)((const long long*)p)[i];
    return ((const int*)p)[i];
}

__device__ __forceinline__ void mma16816(float* c, const uint32_t* a,
                                         const uint32_t* b) {
    asm volatile(
        "mma.sync.aligned.m16n8k16.row.col.f32.bf16.bf16.f32 "
        "{%0,%1,%2,%3}, {%4,%5,%6,%7}, {%8,%9}, {%0,%1,%2,%3};"
        : "+f"(c[0]), "+f"(c[1]), "+f"(c[2]), "+f"(c[3])
        : "r"(a[0]), "r"(a[1]), "r"(a[2]), "r"(a[3]), "r"(b[0]), "r"(b[1]));
}

__device__ __forceinline__ uint32_t smem_u32(const void* p) {
    uint32_t a;
    asm("{ .reg .u64 t; cvta.to.shared.u64 t, %1; cvt.u32.u64 %0, t; }"
        : "=r"(a) : "l"(p));
    return a;
}
__device__ __forceinline__ void cp16(uint32_t dst, const void* src) {
    asm volatile("cp.async.ca.shared.global [%0], [%1], 16;"
                 :: "r"(dst), "l"(src) : "memory");
}
#define CP_COMMIT() asm volatile("cp.async.commit_group;" ::: "memory")
#define CP_WAIT(N)  asm volatile("cp.async.wait_group %0;" :: "n"(N) : "memory")

// ---------------------------------------------------------------------------
__global__ void detect_kernel(const int* __restrict__ ei32) {
    if (threadIdx.x == 0 && blockIdx.x == 0) {
        int nz = 0;
        #pragma unroll
        for (int i = 1; i < 256; i += 2) nz |= (ei32[i] != 0);
        g_is64 = (nz == 0) ? 1 : 0;
    }
}

__global__ void init_kernel(int n) {
    int i = blockIdx.x * blockDim.x + threadIdx.x;
    if (i < n) g_degi[i] = 0;
    if (i < GRAPHS * C) g_sums[i] = 0.f;
    if (i < GRAPHS) g_counts[i] = 0.f;
}

__global__ void degi_kernel(const void* __restrict__ ei, int E) {
    int i = blockIdx.x * blockDim.x + threadIdx.x;
    if (i >= E) return;
    int d = load_idx(ei, (long long)E + i, g_is64);
    atomicAdd(&g_degi[d], 1);
}

// ---------------- hierarchical scan ----------------------------------------
__global__ void scan1_kernel(int n) {
    __shared__ int wsum[32];
    int t = threadIdx.x;
    int i = blockIdx.x * 1024 + t;
    int v = (i < n) ? g_degi[i] : 0;
    int lane = t & 31, w = t >> 5;
    int inc = v;
    #pragma unroll
    for (int d = 1; d < 32; d <<= 1) {
        int u = __shfl_up_sync(0xFFFFFFFFu, inc, d);
        if (lane >= d) inc += u;
    }
    if (lane == 31) wsum[w] = inc;
    __syncthreads();
    if (w == 0) {
        int x = wsum[lane];
        #pragma unroll
        for (int d = 1; d < 32; d <<= 1) {
            int u = __shfl_up_sync(0xFFFFFFFFu, x, d);
            if (lane >= d) x += u;
        }
        wsum[lane] = x;
    }
    __syncthreads();
    int excl = inc - v + (w ? wsum[w - 1] : 0);
    if (i < n) g_rowptr[i] = excl;
    if (t == 1023) g_bsum[blockIdx.x] = excl + v;
}

__global__ void scan2_kernel(int nb) {
    __shared__ int wsum[32];
    int t = threadIdx.x;                     // 1024 threads
    int v = (t < nb) ? g_bsum[t] : 0;
    int lane = t & 31, w = t >> 5;
    int inc = v;
    #pragma unroll
    for (int d = 1; d < 32; d <<= 1) {
        int u = __shfl_up_sync(0xFFFFFFFFu, inc, d);
        if (lane >= d) inc += u;
    }
    if (lane == 31) wsum[w] = inc;
    __syncthreads();
    if (w == 0) {
        int x = wsum[lane];
        #pragma unroll
        for (int d = 1; d < 32; d <<= 1) {
            int u = __shfl_up_sync(0xFFFFFFFFu, x, d);
            if (lane >= d) x += u;
        }
        wsum[lane] = x;
    }
    __syncthreads();
    int excl = inc - v + (w ? wsum[w - 1] : 0);
    if (t < nb) g_bsum[t] = excl;
}

__global__ void scan3_kernel(int n) {
    int i = blockIdx.x * blockDim.x + threadIdx.x;
    if (i >= n) return;
    int d = g_degi[i];
    int r = g_rowptr[i] + g_bsum[i >> 10];
    g_rowptr[i] = r;
    g_cursor[i] = r;
    g_dinv[i] = rsqrtf((float)d + 1.f);
    if (i == n - 1) g_rowptr[n] = r + d;
}

__global__ void place_kernel(const void* __restrict__ ei, int E) {
    int e = blockIdx.x * blockDim.x + threadIdx.x;
    if (e >= E) return;
    int is64 = g_is64;
    int src = load_idx(ei, e, is64);
    int dst = load_idx(ei, (long long)E + e, is64);
    int pos = atomicAdd(&g_cursor[dst], 1);
    g_elist[pos] = src;
}

// ---------------------------------------------------------------------------
// A = bf16(x * dinv[row]), rows >= n zero-padded. 8 channels per thread.
__global__ void convert_kernel(const float* __restrict__ x, int n) {
    long long idx = (long long)blockIdx.x * blockDim.x + threadIdx.x;
    if (idx >= (long long)NODES_PAD * 32) return;
    int row = (int)(idx >> 5);
    int p = (int)(idx & 31);            // 8-channel group
    uint4 outv;
    if (row < n) {
        float d = g_dinv[row];
        float4 v0 = *(const float4*)(x + (size_t)row * C + p * 8);
        float4 v1 = *(const float4*)(x + (size_t)row * C + p * 8 + 4);
        __nv_bfloat162 h0 = __float22bfloat162_rn(make_float2(v0.x * d, v0.y * d));
        __nv_bfloat162 h1 = __float22bfloat162_rn(make_float2(v0.z * d, v0.w * d));
        __nv_bfloat162 h2 = __float22bfloat162_rn(make_float2(v1.x * d, v1.y * d));
        __nv_bfloat162 h3 = __float22bfloat162_rn(make_float2(v1.z * d, v1.w * d));
        outv = make_uint4(*(uint32_t*)&h0, *(uint32_t*)&h1,
                          *(uint32_t*)&h2, *(uint32_t*)&h3);
    } else {
        outv = make_uint4(0, 0, 0, 0);
    }
    *(uint4*)(g_A + (size_t)row * C + p * 8) = outv;
}

// B rows nn: bf16(W1[:, nn]), K-major [nn][k]
__global__ void bbuild_kernel(const float* __restrict__ W1) {
    int idx = blockIdx.x * blockDim.x + threadIdx.x;
    if (idx >= C * C) return;
    int nn = idx >> 8, k = idx & 255;
    g_B[(size_t)nn * C + k] = __float2bfloat16(W1[(size_t)k * C + nn]);
}

// ---------------------------------------------------------------------------
// bf16 mma.sync GEMM, K=256, cp.async double buffered; CTA tile 128x128 so
// 2 CTAs/SM co-reside (73.7KB smem) and hide each other's load/sync bubbles.
// Warp grid 2(M) x 4(N); warp tile 64x32. Epilogue packs bf16x2.
#define APAD 72
#define STG_ELEMS ((128 + 128) * APAD)

__device__ __forceinline__ void load_stage(uint32_t sbase, int tid, int m0,
                                           int n0, int kc, int s) {
    uint32_t As = sbase + (uint32_t)(s * STG_ELEMS) * 2;
    uint32_t Bs = As + 128 * APAD * 2;
    const __nv_bfloat16* Ab = g_A + (size_t)m0 * C + kc * 64;
    #pragma unroll
    for (int i = 0; i < 4; i++) {
        int u = tid + i * 256;
        int r = u >> 3, o = u & 7;
        cp16(As + (uint32_t)(r * APAD + o * 8) * 2,
             Ab + (size_t)r * C + o * 8);
    }
    const __nv_bfloat16* Bb = g_B + (size_t)n0 * C + kc * 64;
    #pragma unroll
    for (int i = 0; i < 4; i++) {
        int u = tid + i * 256;
        int r = u >> 3, o = u & 7;
        cp16(Bs + (uint32_t)(r * APAD + o * 8) * 2,
             Bb + (size_t)r * C + o * 8);
    }
    CP_COMMIT();
}

__global__ void __launch_bounds__(256) gemm_mma_kernel() {
    extern __shared__ __nv_bfloat16 smem[];

    int tid = threadIdx.x;
    int wid = tid >> 5, lane = tid & 31;
    int g = lane >> 2, tir = lane & 3;
    int wm = wid & 1, wn = wid >> 1;          // warp grid 2 x 4
    int m0 = blockIdx.x * 128;
    int n0 = blockIdx.y * 128;

    uint32_t sbase = smem_u32(smem);
    const int NKC = C / 64;                   // 4 chunks

    float c[4][4][4];
    #pragma unroll
    for (int mt = 0; mt < 4; mt++)
        #pragma unroll
        for (int nt = 0; nt < 4; nt++)
            #pragma unroll
            for (int q = 0; q < 4; q++) c[mt][nt][q] = 0.f;

    load_stage(sbase, tid, m0, n0, 0, 0);

    for (int kc = 0; kc < NKC; kc++) {
        if (kc + 1 < NKC) {
            load_stage(sbase, tid, m0, n0, kc + 1, (kc + 1) & 1);
            CP_WAIT(1);
        } else {
            CP_WAIT(0);
        }
        __syncthreads();

        const __nv_bfloat16* As = smem + (kc & 1) * STG_ELEMS;
        const __nv_bfloat16* Bs = As + 128 * APAD;

        #pragma unroll
        for (int ks = 0; ks < 4; ks++) {
            int kof = ks * 16 + tir * 2;
            uint32_t a[4][4];
            #pragma unroll
            for (int mt = 0; mt < 4; mt++) {
                int base = (wm * 64 + mt * 16 + g) * APAD + kof;
                a[mt][0] = *(const uint32_t*)(As + base);
                a[mt][1] = *(const uint32_t*)(As + base + 8 * APAD);
                a[mt][2] = *(const uint32_t*)(As + base + 8);
                a[mt][3] = *(const uint32_t*)(As + base + 8 * APAD + 8);
            }
            uint32_t b[4][2];
            #pragma unroll
            for (int nt = 0; nt < 4; nt++) {
                int base = (wn * 32 + nt * 8 + g) * APAD + kof;
                b[nt][0] = *(const uint32_t*)(Bs + base);
                b[nt][1] = *(const uint32_t*)(Bs + base + 8);
            }
            #pragma unroll
            for (int mt = 0; mt < 4; mt++)
                #pragma unroll
                for (int nt = 0; nt < 4; nt++)
                    mma16816(c[mt][nt], a[mt], b[nt]);
        }
        __syncthreads();
    }

    // epilogue: pack fp32 pair -> bf16x2, single 4B store per fragment half
    #pragma unroll
    for (int mt = 0; mt < 4; mt++) {
        int row = m0 + wm * 64 + mt * 16 + g;
        #pragma unroll
        for (int nt = 0; nt < 4; nt++) {
            int col2 = n0 / 2 + wn * 16 + nt * 4 + tir;   // (col)/2, col even
            __nv_bfloat162 p0 = __float22bfloat162_rn(
                make_float2(c[mt][nt][0], c[mt][nt][1]));
            __nv_bfloat162 p1 = __float22bfloat162_rn(
                make_float2(c[mt][nt][2], c[mt][nt][3]));
            g_hsb[(size_t)row * (C / 2) + col2]       = *(uint32_t*)&p0;
            g_hsb[(size_t)(row + 8) * (C / 2) + col2] = *(uint32_t*)&p1;
        }
    }
}

// ---------------------------------------------------------------------------
// fused CSR gather + relu + sorted-run mean-pool, uint2-wide (R12 shape).
// Block = 128 threads in two halves: half h (64 threads) processes nodes
// start+h, start+h+2, ... Each thread owns one uint2 word = 4 channels, so
// 64 threads cover a full 512B row; a warp reads 256B (2 lines) per LDG.
// NPB=32: 3125 blocks for better latency hiding / tail balance.
#define NPB 32
__global__ void __launch_bounds__(128) gather_pool_kernel(
        const void* __restrict__ batch, const float* __restrict__ b1, int n) {
    int t = threadIdx.x;
    int h = t >> 6;                      // node-parity half
    int q = t & 63;                      // uint2 word index; channels 4q..4q+3
    int start = blockIdx.x * NPB;
    if (start >= n) return;
    int end = min(start + NPB, n);
    int is64 = g_is64;

    float b0 = b1[4 * q + 0], bq1 = b1[4 * q + 1];
    float b2v = b1[4 * q + 2], b3v = b1[4 * q + 3];

    int first = start + h;
    if (first >= end) return;
    int gp = load_idx(batch, first, is64);
    float acc0 = 0.f, acc1 = 0.f, acc2 = 0.f, acc3 = 0.f;

    for (int i = first; i < end; i += 2) {
        int gid = load_idx(batch, i, is64);
        if (gid != gp) {
            atomicAdd(&g_sums[gp * C + 4 * q + 0], acc0);
            atomicAdd(&g_sums[gp * C + 4 * q + 1], acc1);
            atomicAdd(&g_sums[gp * C + 4 * q + 2], acc2);
            atomicAdd(&g_sums[gp * C + 4 * q + 3], acc3);
            acc0 = acc1 = acc2 = acc3 = 0.f;
            gp = gid;
        }

        int r0 = g_rowptr[i], r1 = g_rowptr[i + 1];
        uint2 w = ((const uint2*)(g_hsb + (size_t)i * 128))[q];   // self-loop
        float2 fa = __bfloat1622float2(*(__nv_bfloat162*)&w.x);
        float2 fb = __bfloat1622float2(*(__nv_bfloat162*)&w.y);
        float s0 = fa.x, s1 = fa.y, s2 = fb.x, s3 = fb.y;
        float u0 = 0.f, u1 = 0.f, u2 = 0.f, u3 = 0.f;

        int j = r0;
        for (; j + 4 <= r1; j += 4) {
            int e0 = g_elist[j],     e1 = g_elist[j + 1];
            int e2 = g_elist[j + 2], e3 = g_elist[j + 3];
            uint2 w0 = ((const uint2*)(g_hsb + (size_t)e0 * 128))[q];
            uint2 w1 = ((const uint2*)(g_hsb + (size_t)e1 * 128))[q];
            uint2 w2 = ((const uint2*)(g_hsb + (size_t)e2 * 128))[q];
            uint2 w3 = ((const uint2*)(g_hsb + (size_t)e3 * 128))[q];
            float2 a0 = __bfloat1622float2(*(__nv_bfloat162*)&w0.x);
            float2 a1 = __bfloat1622float2(*(__nv_bfloat162*)&w0.y);
            float2 c0 = __bfloat1622float2(*(__nv_bfloat162*)&w1.x);
            float2 c1 = __bfloat1622float2(*(__nv_bfloat162*)&w1.y);
            float2 d0 = __bfloat1622float2(*(__nv_bfloat162*)&w2.x);
            float2 d1 = __bfloat1622float2(*(__nv_bfloat162*)&w2.y);
            float2 e0f = __bfloat1622float2(*(__nv_bfloat162*)&w3.x);
            float2 e1f = __bfloat1622float2(*(__nv_bfloat162*)&w3.y);
            s0 += a0.x + d0.x; s1 += a0.y + d0.y;
            s2 += a1.x + d1.x; s3 += a1.y + d1.y;
            u0 += c0.x + e0f.x; u1 += c0.y + e0f.y;
            u2 += c1.x + e1f.x; u3 += c1.y + e1f.y;
        }
        for (; j < r1; j++) {
            uint2 wj = ((const uint2*)(g_hsb + (size_t)g_elist[j] * 128))[q];
            float2 a0 = __bfloat1622float2(*(__nv_bfloat162*)&wj.x);
            float2 a1 = __bfloat1622float2(*(__nv_bfloat162*)&wj.y);
            s0 += a0.x; s1 += a0.y; s2 += a1.x; s3 += a1.y;
        }

        float di = g_dinv[i];
        acc0 += fmaxf(di * (s0 + u0) + b0, 0.f);
        acc1 += fmaxf(di * (s1 + u1) + bq1, 0.f);
        acc2 += fmaxf(di * (s2 + u2) + b2v, 0.f);
        acc3 += fmaxf(di * (s3 + u3) + b3v, 0.f);
    }
    atomicAdd(&g_sums[gp * C + 4 * q + 0], acc0);
    atomicAdd(&g_sums[gp * C + 4 * q + 1], acc1);
    atomicAdd(&g_sums[gp * C + 4 * q + 2], acc2);
    atomicAdd(&g_sums[gp * C + 4 * q + 3], acc3);
}

// ---------------------------------------------------------------------------
// counts: register run-length accumulation, one thread per 64 nodes
__global__ void bcount_kernel(const void* __restrict__ batch, int n) {
    int seg = (blockIdx.x * blockDim.x + threadIdx.x);
    int start = seg * 64;
    if (start >= n) return;
    int end = min(start + 64, n);
    int is64 = g_is64;
    int gp = load_idx(batch, start, is64);
    float cnt = 0.f;
    for (int i = start; i < end; i++) {
        int g = load_idx(batch, i, is64);
        if (g != gp) { atomicAdd(&g_counts[gp], cnt); cnt = 0.f; gp = g; }
        cnt += 1.f;
    }
    atomicAdd(&g_counts[gp], cnt);
}

__global__ void final_kernel(const float* __restrict__ W2,
                             const float* __restrict__ b2,
                             float* __restrict__ out) {
    int t = threadIdx.x;
    if (t >= GRAPHS * OUTC) return;
    int g = t / OUTC, o = t % OUTC;
    float s = 0.f;
    #pragma unroll 8
    for (int k = 0; k < C; k++)
        s += g_sums[g * C + k] * W2[k * OUTC + o];
    out[t] = s / fmaxf(g_counts[g], 1.f) + b2[o];
}

// ---------------------------------------------------------------------------
extern "C" void kernel_launch(void* const* d_in, const int* in_sizes, int n_in,
                              void* d_out, int out_size) {
    const float* x     = (const float*)d_in[0];
    const void*  ei    = d_in[1];
    const void*  batch = d_in[2];
    const float* W1    = (const float*)d_in[3];
    const float* b1    = (const float*)d_in[4];
    const float* W2    = (const float*)d_in[5];
    const float* b2    = (const float*)d_in[6];
    float* out = (float*)d_out;

    int n = in_sizes[0] / C;    // 100000
    int E = in_sizes[1] / 2;    // 1600000
    int nb = (n + 1023) / 1024;

    detect_kernel<<<1, 32>>>((const int*)ei);
    init_kernel<<<(n + 255) / 256, 256>>>(n);
    degi_kernel<<<(E + 255) / 256, 256>>>(ei, E);
    scan1_kernel<<<nb, 1024>>>(n);
    scan2_kernel<<<1, 1024>>>(nb);
    scan3_kernel<<<(n + 255) / 256, 256>>>(n);

    convert_kernel<<<(NODES_PAD * 32 + 255) / 256, 256>>>(x, n);
    bbuild_kernel<<<256, 256>>>(W1);

    static const int SMEM_BYTES = 2 * STG_ELEMS * 2;   // 73728
    cudaFuncSetAttribute(gemm_mma_kernel,
                         cudaFuncAttributeMaxDynamicSharedMemorySize, SMEM_BYTES);
    dim3 ggrid(NODES_PAD / 128, 2);
    gemm_mma_kernel<<<ggrid, 256, SMEM_BYTES>>>();

    place_kernel<<<(E + 255) / 256, 256>>>(ei, E);
    bcount_kernel<<<(n / 64 + 255) / 256, 256>>>(batch, n);
    gather_pool_kernel<<<(n + NPB - 1) / NPB, 128>>>(batch, b1, n);
    final_kernel<<<1, 640>>>(W2, b2, out);
}